// round 11
// baseline (speedup 1.0000x reference)
#include <cuda_runtime.h>

// out[b, y, x] = in[b, y + dyi[b], x - dxi[b]] if in-bounds else 0
// B=1024, WIN=256, C=1, fp32.
//
// One warp per QUAD of adjacent rows (same batch). All 8 wide loads issued
// up front (MLP=8, 4KB contiguous read window per warp), then rows retired
// one at a time to bound live registers. 4KB contiguous write per warp.
// Goal: DRAM page locality / controller efficiency, not more parallelism.

static constexpr int WIN = 256;

__device__ __forceinline__ void emit_row(
    float4 a0, float4 a1, int s, int q0, int lane,
    const float4* __restrict__ src, bool rowok, int sx0,
    float4* __restrict__ dst)
{
    // a2 = next lane's a0 (lane 31 loads its own)
    float4 a2;
    a2.x = __shfl_down_sync(0xffffffffu, a0.x, 1);
    a2.y = __shfl_down_sync(0xffffffffu, a0.y, 1);
    a2.z = __shfl_down_sync(0xffffffffu, a0.z, 1);
    a2.w = __shfl_down_sync(0xffffffffu, a0.w, 1);
    if (lane == 31) {
        int c2 = q0 + 2 < 0 ? 0 : (q0 + 2 > 63 ? 63 : q0 + 2);
        a2 = __ldg(src + c2);
    }

    float4 o0, o1;
    if (s == 0)      { o0 = a0; o1 = a1; }
    else if (s == 1) { o0 = make_float4(a0.y, a0.z, a0.w, a1.x);
                       o1 = make_float4(a1.y, a1.z, a1.w, a2.x); }
    else if (s == 2) { o0 = make_float4(a0.z, a0.w, a1.x, a1.y);
                       o1 = make_float4(a1.z, a1.w, a2.x, a2.y); }
    else             { o0 = make_float4(a0.w, a1.x, a1.y, a1.z);
                       o1 = make_float4(a1.w, a2.x, a2.y, a2.z); }

    unsigned base = rowok ? (unsigned)sx0 : 0xC0000000u;
    if (base + 0u >= (unsigned)WIN) o0.x = 0.f;
    if (base + 1u >= (unsigned)WIN) o0.y = 0.f;
    if (base + 2u >= (unsigned)WIN) o0.z = 0.f;
    if (base + 3u >= (unsigned)WIN) o0.w = 0.f;
    if (base + 4u >= (unsigned)WIN) o1.x = 0.f;
    if (base + 5u >= (unsigned)WIN) o1.y = 0.f;
    if (base + 6u >= (unsigned)WIN) o1.z = 0.f;
    if (base + 7u >= (unsigned)WIN) o1.w = 0.f;

    dst[0] = o0;
    dst[1] = o1;
}

__global__ __launch_bounds__(256, 4) void translation_kernel(
    const float4* __restrict__ in4,
    const float* __restrict__ dx,
    const float* __restrict__ dy,
    float4* __restrict__ out4)
{
    int idx  = blockIdx.x * blockDim.x + threadIdx.x;
    int lane = idx & 31;
    int quad = idx >> 5;              // row-quad index
    int b    = quad >> 6;             // 64 quads per batch
    int y0   = (quad & 63) << 2;      // first row of the quad

    int dxi = (int)dx[b];             // trunc toward zero == astype(int32)
    int dyi = (int)dy[b];

    int sy0 = y0 + dyi;
    bool ok0 = (unsigned)(sy0 + 0) < (unsigned)WIN;
    bool ok1 = (unsigned)(sy0 + 1) < (unsigned)WIN;
    bool ok2 = (unsigned)(sy0 + 2) < (unsigned)WIN;
    bool ok3 = (unsigned)(sy0 + 3) < (unsigned)WIN;

    const float4* base = in4 + (b << 14);
    const float4* src0 = base + ((ok0 ? sy0 + 0 : 0) << 6);
    const float4* src1 = base + ((ok1 ? sy0 + 1 : 0) << 6);
    const float4* src2 = base + ((ok2 ? sy0 + 2 : 0) << 6);
    const float4* src3 = base + ((ok3 ? sy0 + 3 : 0) << 6);

    int x0  = lane << 3;
    int sx0 = x0 - dxi;
    int q0  = sx0 >> 2;
    int s   = sx0 & 3;                // warp-uniform

    int c0 = q0     < 0 ? 0 : (q0     > 63 ? 63 : q0);
    int c1 = q0 + 1 < 0 ? 0 : (q0 + 1 > 63 ? 63 : q0 + 1);

    // 8 independent wide loads up front (4KB contiguous read window per warp)
    float4 A0 = __ldg(src0 + c0);
    float4 A1 = __ldg(src0 + c1);
    float4 B0 = __ldg(src1 + c0);
    float4 B1 = __ldg(src1 + c1);
    float4 C0 = __ldg(src2 + c0);
    float4 C1 = __ldg(src2 + c1);
    float4 D0 = __ldg(src3 + c0);
    float4 D1 = __ldg(src3 + c1);

    int row0 = (b << 8) | y0;
    float4* dst = out4 + (row0 << 6) + (lane << 1);

    // retire rows one at a time (bounds live registers)
    emit_row(A0, A1, s, q0, lane, src0, ok0, sx0, dst);
    emit_row(B0, B1, s, q0, lane, src1, ok1, sx0, dst + 64);
    emit_row(C0, C1, s, q0, lane, src2, ok2, sx0, dst + 128);
    emit_row(D0, D1, s, q0, lane, src3, ok3, sx0, dst + 192);
}

extern "C" void kernel_launch(void* const* d_in, const int* in_sizes, int n_in,
                              void* d_out, int out_size)
{
    const float4* in  = (const float4*)d_in[0];
    const float*  dx  = (const float*)d_in[1];
    const float*  dy  = (const float*)d_in[2];
    float4*       out = (float4*)d_out;

    // warps = B*WIN/4 = 65536 ; threads = 2,097,152
    int threads = 256;
    int blocks  = (1024 * 64 * 32) / threads;   // 8192
    translation_kernel<<<blocks, threads>>>(in, dx, dy, out);
}

// round 12
// speedup vs baseline: 1.0191x; 1.0191x over previous
#include <cuda_runtime.h>

// out[b, y, x] = in[b, y + dyi[b], x - dxi[b]] if in-bounds else 0
// B=1024, WIN=256, C=1, fp32.
//
// One warp per QUAD of adjacent rows. 8 wide loads up front (MLP=8), rows
// retired one at a time. OOB loads are PREDICATED OFF (not clamped): garbage
// registers are masked to zero downstream, saving ~10% of load issue and the
// duplicate L2 traffic. Streaming cache hints (no reuse in this kernel).

static constexpr int WIN = 256;

__device__ __forceinline__ void emit_row(
    float4 a0, float4 a1, int s, int q0, int lane,
    const float4* __restrict__ src, bool rowok, int sx0,
    float4* __restrict__ dst)
{
    // a2 = next lane's a0 (lane 31 loads its own, only if needed & valid)
    float4 a2;
    a2.x = __shfl_down_sync(0xffffffffu, a0.x, 1);
    a2.y = __shfl_down_sync(0xffffffffu, a0.y, 1);
    a2.z = __shfl_down_sync(0xffffffffu, a0.z, 1);
    a2.w = __shfl_down_sync(0xffffffffu, a0.w, 1);
    if (lane == 31 && rowok && (unsigned)(q0 + 2) < 64u)
        a2 = __ldcs(src + q0 + 2);

    float4 o0, o1;
    if (s == 0)      { o0 = a0; o1 = a1; }
    else if (s == 1) { o0 = make_float4(a0.y, a0.z, a0.w, a1.x);
                       o1 = make_float4(a1.y, a1.z, a1.w, a2.x); }
    else if (s == 2) { o0 = make_float4(a0.z, a0.w, a1.x, a1.y);
                       o1 = make_float4(a1.z, a1.w, a2.x, a2.y); }
    else             { o0 = make_float4(a0.w, a1.x, a1.y, a1.z);
                       o1 = make_float4(a1.w, a2.x, a2.y, a2.z); }

    unsigned base = rowok ? (unsigned)sx0 : 0xC0000000u;
    if (base + 0u >= (unsigned)WIN) o0.x = 0.f;
    if (base + 1u >= (unsigned)WIN) o0.y = 0.f;
    if (base + 2u >= (unsigned)WIN) o0.z = 0.f;
    if (base + 3u >= (unsigned)WIN) o0.w = 0.f;
    if (base + 4u >= (unsigned)WIN) o1.x = 0.f;
    if (base + 5u >= (unsigned)WIN) o1.y = 0.f;
    if (base + 6u >= (unsigned)WIN) o1.z = 0.f;
    if (base + 7u >= (unsigned)WIN) o1.w = 0.f;

    __stcs(dst + 0, o0);
    __stcs(dst + 1, o1);
}

__global__ __launch_bounds__(256, 4) void translation_kernel(
    const float4* __restrict__ in4,
    const float* __restrict__ dx,
    const float* __restrict__ dy,
    float4* __restrict__ out4)
{
    int idx  = blockIdx.x * blockDim.x + threadIdx.x;
    int lane = idx & 31;
    int quad = idx >> 5;              // row-quad index
    int b    = quad >> 6;             // 64 quads per batch
    int y0   = (quad & 63) << 2;      // first row of the quad

    int dxi = (int)dx[b];             // trunc toward zero == astype(int32)
    int dyi = (int)dy[b];

    int sy0 = y0 + dyi;
    bool ok0 = (unsigned)(sy0 + 0) < (unsigned)WIN;
    bool ok1 = (unsigned)(sy0 + 1) < (unsigned)WIN;
    bool ok2 = (unsigned)(sy0 + 2) < (unsigned)WIN;
    bool ok3 = (unsigned)(sy0 + 3) < (unsigned)WIN;

    const float4* base = in4 + (b << 14);
    const float4* src0 = base + ((ok0 ? sy0 + 0 : 0) << 6);
    const float4* src1 = base + ((ok1 ? sy0 + 1 : 0) << 6);
    const float4* src2 = base + ((ok2 ? sy0 + 2 : 0) << 6);
    const float4* src3 = base + ((ok3 ? sy0 + 3 : 0) << 6);

    int x0  = lane << 3;
    int sx0 = x0 - dxi;
    int q0  = sx0 >> 2;
    int s   = sx0 & 3;                // warp-uniform

    bool v0 = (unsigned)q0       < 64u;   // chunk 0 in-bounds
    bool v1 = (unsigned)(q0 + 1) < 64u;   // chunk 1 in-bounds

    // predicated wide loads: garbage registers are masked downstream
    float4 A0, A1, B0, B1, C0, C1, D0, D1;
    if (ok0 && v0) A0 = __ldcs(src0 + q0);
    if (ok0 && v1) A1 = __ldcs(src0 + q0 + 1);
    if (ok1 && v0) B0 = __ldcs(src1 + q0);
    if (ok1 && v1) B1 = __ldcs(src1 + q0 + 1);
    if (ok2 && v0) C0 = __ldcs(src2 + q0);
    if (ok2 && v1) C1 = __ldcs(src2 + q0 + 1);
    if (ok3 && v0) D0 = __ldcs(src3 + q0);
    if (ok3 && v1) D1 = __ldcs(src3 + q0 + 1);

    int row0 = (b << 8) | y0;
    float4* dst = out4 + (row0 << 6) + (lane << 1);

    emit_row(A0, A1, s, q0, lane, src0, ok0, sx0, dst);
    emit_row(B0, B1, s, q0, lane, src1, ok1, sx0, dst + 64);
    emit_row(C0, C1, s, q0, lane, src2, ok2, sx0, dst + 128);
    emit_row(D0, D1, s, q0, lane, src3, ok3, sx0, dst + 192);
}

extern "C" void kernel_launch(void* const* d_in, const int* in_sizes, int n_in,
                              void* d_out, int out_size)
{
    const float4* in  = (const float4*)d_in[0];
    const float*  dx  = (const float*)d_in[1];
    const float*  dy  = (const float*)d_in[2];
    float4*       out = (float4*)d_out;

    // warps = B*WIN/4 = 65536 ; threads = 2,097,152
    int threads = 256;
    int blocks  = (1024 * 64 * 32) / threads;   // 8192
    translation_kernel<<<blocks, threads>>>(in, dx, dy, out);
}